// round 6
// baseline (speedup 1.0000x reference)
#include <cuda_runtime.h>
#include <math.h>

#define BATCH 4
#define SEQ   4096
#define EMB   512
#define HD    64
#define NSPLIT 7

__device__ float g_q[BATCH * SEQ * HD];
__device__ float g_k[BATCH * SEQ * HD];
__device__ float g_v[BATCH * SEQ * HD];
__device__ float g_part[NSPLIT * BATCH * SEQ * HD];   // unnormalized O partials
__device__ float g_lsum[NSPLIT * BATCH * SEQ];        // exp-sum partials

// ---------------------------------------------------------------------------
__device__ __forceinline__ unsigned f2tf(float x) {
    unsigned r;
    asm("cvt.rna.tf32.f32 %0, %1;" : "=r"(r) : "f"(x));
    return r;
}
__device__ __forceinline__ float ex2(float x) {
    float r;
    asm("ex2.approx.ftz.f32 %0, %1;" : "=f"(r) : "f"(x));
    return r;
}

__device__ __forceinline__ void mma_tf32(float c[4],
                                         unsigned a0, unsigned a1,
                                         unsigned a2, unsigned a3,
                                         unsigned b0, unsigned b1) {
    asm volatile(
        "mma.sync.aligned.m16n8k8.row.col.f32.tf32.tf32.f32 "
        "{%0,%1,%2,%3}, {%4,%5,%6,%7}, {%8,%9}, {%0,%1,%2,%3};"
        : "+f"(c[0]), "+f"(c[1]), "+f"(c[2]), "+f"(c[3])
        : "r"(a0), "r"(a1), "r"(a2), "r"(a3), "r"(b0), "r"(b1));
}

#define CP_COMMIT() asm volatile("cp.async.commit_group;" ::: "memory")
#define CP_WAIT1()  asm volatile("cp.async.wait_group 1;" ::: "memory")

// ---------------------------------------------------------------------------
// tf32 projection, cp.async double-buffered, K-chunks of 32.
// C[16384,64] = X[16384,512] * W[64,512]^T ; outputs stored tf32-rounded.
// ---------------------------------------------------------------------------
#define PP   36
#define PBUF (64 * PP)
#define PROJ_SMEM_BYTES (4 * PBUF * 4)
#define NCHUNK (EMB / 32)   // 16

__device__ __forceinline__ void proj_load_async(float* Xd, float* Wd,
                                                const float* xs, const float* ws,
                                                int tid) {
    unsigned xa = (unsigned)__cvta_generic_to_shared(Xd);
    unsigned wa = (unsigned)__cvta_generic_to_shared(Wd);
    #pragma unroll
    for (int i = 0; i < 4; i++) {
        int f = tid + 128 * i;           // 512 float4 = 64 rows x 8
        int row = f >> 3, c4 = f & 7;
        asm volatile("cp.async.cg.shared.global [%0], [%1], 16;" ::
            "r"(xa + (unsigned)((row * PP + c4 * 4) * 4)),
            "l"(xs + (size_t)row * EMB + c4 * 4) : "memory");
        asm volatile("cp.async.cg.shared.global [%0], [%1], 16;" ::
            "r"(wa + (unsigned)((row * PP + c4 * 4) * 4)),
            "l"(ws + (size_t)row * EMB + c4 * 4) : "memory");
    }
}

__global__ __launch_bounds__(128) void proj_mma_kernel(
    const float* __restrict__ x,
    const float* __restrict__ WQ,
    const float* __restrict__ WK,
    const float* __restrict__ WV)
{
    extern __shared__ float psm[];
    float* Xb[2] = { psm, psm + PBUF };
    float* Wb[2] = { psm + 2 * PBUF, psm + 3 * PBUF };

    const float* W;
    float* out;
    if (blockIdx.y == 0)      { W = WQ; out = g_q; }
    else if (blockIdx.y == 1) { W = WK; out = g_k; }
    else                      { W = WV; out = g_v; }

    const int tid  = threadIdx.x;
    const int lane = tid & 31;
    const int warp = tid >> 5;
    const int g    = lane >> 2;
    const int tq   = lane & 3;
    const int bm   = blockIdx.x * 64;
    const int r0   = 16 * warp + g;

    const float* xrow = x + (size_t)bm * EMB;

    float acc[8][4];
    #pragma unroll
    for (int n = 0; n < 8; n++)
        #pragma unroll
        for (int j = 0; j < 4; j++) acc[n][j] = 0.0f;

    proj_load_async(Xb[0], Wb[0], xrow, W, tid);
    CP_COMMIT();

    for (int c = 0; c < NCHUNK; c++) {
        __syncthreads();
        if (c + 1 < NCHUNK)
            proj_load_async(Xb[(c + 1) & 1], Wb[(c + 1) & 1],
                            xrow + (c + 1) * 32, W + (c + 1) * 32, tid);
        CP_COMMIT();
        CP_WAIT1();
        __syncthreads();

        const float* Xf = Xb[c & 1];
        const float* Wf = Wb[c & 1];

        unsigned xa[4][4];
        #pragma unroll
        for (int ks = 0; ks < 4; ks++) {
            int kk = ks * 8;
            xa[ks][0] = f2tf(Xf[(r0)     * PP + kk + tq]);
            xa[ks][1] = f2tf(Xf[(r0 + 8) * PP + kk + tq]);
            xa[ks][2] = f2tf(Xf[(r0)     * PP + kk + tq + 4]);
            xa[ks][3] = f2tf(Xf[(r0 + 8) * PP + kk + tq + 4]);
        }
        #pragma unroll
        for (int n = 0; n < 8; n++) {
            #pragma unroll
            for (int ks = 0; ks < 4; ks++) {
                unsigned b0 = f2tf(Wf[(8 * n + g) * PP + 8 * ks + tq]);
                unsigned b1 = f2tf(Wf[(8 * n + g) * PP + 8 * ks + tq + 4]);
                mma_tf32(acc[n], xa[ks][0], xa[ks][1], xa[ks][2], xa[ks][3], b0, b1);
            }
        }
    }

    // store outputs PRE-ROUNDED to tf32 (attention consumes without cvt)
    float* o0 = out + (size_t)(bm + r0)     * HD;
    float* o1 = out + (size_t)(bm + r0 + 8) * HD;
    #pragma unroll
    for (int n = 0; n < 8; n++) {
        int cc = 8 * n + 2 * tq;
        float2 w0 = { __uint_as_float(f2tf(acc[n][0])), __uint_as_float(f2tf(acc[n][1])) };
        float2 w1 = { __uint_as_float(f2tf(acc[n][2])), __uint_as_float(f2tf(acc[n][3])) };
        *reinterpret_cast<float2*>(&o0[cc]) = w0;
        *reinterpret_cast<float2*>(&o1[cc]) = w1;
    }
}

// ---------------------------------------------------------------------------
// Attention: tf32 mma, split-KV, cp.async double-buffered K/V,
// shuffle-based S->P fragment conversion (no P smem), no-max softmax.
// ---------------------------------------------------------------------------
#define PK   68
#define PV   72
#define KBUF (64 * PK)
#define VBUF (64 * PV)
#define ATTN_SMEM_BYTES ((2 * KBUF + 2 * VBUF) * 4)

__device__ __forceinline__ void attn_load_async(float* Kd, float* Vd,
                                                const float* kg, const float* vg,
                                                int tid) {
    unsigned ka = (unsigned)__cvta_generic_to_shared(Kd);
    unsigned va = (unsigned)__cvta_generic_to_shared(Vd);
    #pragma unroll
    for (int i = 0; i < 8; i++) {
        int f = tid + 128 * i;           // 1024 float4 = 64 rows x 16
        int row = f >> 4, c4 = f & 15;
        asm volatile("cp.async.cg.shared.global [%0], [%1], 16;" ::
            "r"(ka + (unsigned)((row * PK + c4 * 4) * 4)),
            "l"(kg + row * HD + c4 * 4) : "memory");
        asm volatile("cp.async.cg.shared.global [%0], [%1], 16;" ::
            "r"(va + (unsigned)((row * PV + c4 * 4) * 4)),
            "l"(vg + row * HD + c4 * 4) : "memory");
    }
}

__global__ __launch_bounds__(128, 3) void attn_mma_kernel()
{
    extern __shared__ float sm[];
    float* Kb[2] = { sm, sm + KBUF };
    float* Vb[2] = { sm + 2 * KBUF, sm + 2 * KBUF + VBUF };

    const int tid  = threadIdx.x;
    const int lane = tid & 31;
    const int warp = tid >> 5;
    const int g    = lane >> 2;
    const int tq   = lane & 3;
    const int b    = blockIdx.y;
    const int q0   = blockIdx.x * 64;
    const int z    = blockIdx.z;
    const int t_begin = (64 * z) / NSPLIT;
    const int t_end   = (64 * (z + 1)) / NSPLIT;
    const int nt      = t_end - t_begin;

    const float* qg  = g_q + ((size_t)b * SEQ + q0) * HD;
    const float* kgb = g_k + ((size_t)b * SEQ + (size_t)t_begin * 64) * HD;
    const float* vgb = g_v + ((size_t)b * SEQ + (size_t)t_begin * 64) * HD;

    // Q A-fragments straight from GMEM (values already tf32-rounded by proj)
    const int r0 = 16 * warp + g;
    unsigned qa[8][4];
    #pragma unroll
    for (int ks = 0; ks < 8; ks++) {
        qa[ks][0] = __float_as_uint(qg[(r0)     * HD + 8 * ks + tq]);
        qa[ks][1] = __float_as_uint(qg[(r0 + 8) * HD + 8 * ks + tq]);
        qa[ks][2] = __float_as_uint(qg[(r0)     * HD + 8 * ks + tq + 4]);
        qa[ks][3] = __float_as_uint(qg[(r0 + 8) * HD + 8 * ks + tq + 4]);
    }

    float oacc[8][4];
    #pragma unroll
    for (int n = 0; n < 8; n++)
        #pragma unroll
        for (int j = 0; j < 4; j++) oacc[n][j] = 0.0f;
    float lsum0 = 0.0f, lsum1 = 0.0f;

    // prologue: tile 0 loads in flight
    attn_load_async(Kb[0], Vb[0], kgb, vgb, tid);
    CP_COMMIT();

    const float C = 0.18033688f;   // 0.125 * log2(e)

    for (int tt = 0; tt < nt; tt++) {
        __syncthreads();            // buffer (tt+1)&1 free (its readers done)
        if (tt + 1 < nt)
            attn_load_async(Kb[(tt + 1) & 1], Vb[(tt + 1) & 1],
                            kgb + (size_t)(tt + 1) * 64 * HD,
                            vgb + (size_t)(tt + 1) * 64 * HD, tid);
        CP_COMMIT();
        CP_WAIT1();                 // this tile's copies complete (per-thread)
        __syncthreads();            // all threads' copies visible

        const unsigned* Ku = reinterpret_cast<const unsigned*>(Kb[tt & 1]);
        const unsigned* Vu = reinterpret_cast<const unsigned*>(Vb[tt & 1]);

        #pragma unroll
        for (int nb = 0; nb < 8; nb++) {
            // ---- S block: rows r0/r0+8, cols 8nb..8nb+7 (2-way split chain) ----
            float cfa[4] = {0.f, 0.f, 0.f, 0.f};
            float cfb[4] = {0.f, 0.f, 0.f, 0.f};
            #pragma unroll
            for (int kc = 0; kc < 8; kc += 2) {
                unsigned b0 = Ku[(8 * nb + g) * PK + 8 * kc + tq];
                unsigned b1 = Ku[(8 * nb + g) * PK + 8 * kc + tq + 4];
                mma_tf32(cfa, qa[kc][0], qa[kc][1], qa[kc][2], qa[kc][3], b0, b1);
                unsigned c0 = Ku[(8 * nb + g) * PK + 8 * (kc + 1) + tq];
                unsigned c1 = Ku[(8 * nb + g) * PK + 8 * (kc + 1) + tq + 4];
                mma_tf32(cfb, qa[kc + 1][0], qa[kc + 1][1], qa[kc + 1][2], qa[kc + 1][3], c0, c1);
            }
            float e0 = ex2((cfa[0] + cfb[0]) * C);
            float e1 = ex2((cfa[1] + cfb[1]) * C);
            float e2 = ex2((cfa[2] + cfb[2]) * C);
            float e3 = ex2((cfa[3] + cfb[3]) * C);
            lsum0 += e0 + e1;
            lsum1 += e2 + e3;

            // ---- C-frag -> A-frag conversion via quad shuffles ----
            // need P[r0][8nb+tq], P[r0+8][8nb+tq], P[r0][8nb+tq+4], P[r0+8][8nb+tq+4]
            int h  = tq >> 1;
            float a0 = __shfl_sync(0xffffffffu, e0, h, 4);
            float a1 = __shfl_sync(0xffffffffu, e1, h, 4);
            float b0f = __shfl_sync(0xffffffffu, e0, h + 2, 4);
            float b1f = __shfl_sync(0xffffffffu, e1, h + 2, 4);
            float c0f = __shfl_sync(0xffffffffu, e2, h, 4);
            float c1f = __shfl_sync(0xffffffffu, e3, h, 4);
            float d0f = __shfl_sync(0xffffffffu, e2, h + 2, 4);
            float d1f = __shfl_sync(0xffffffffu, e3, h + 2, 4);
            bool odd = (tq & 1);
            unsigned pa0 = f2tf(odd ? a1 : a0);   // P[r0][8nb+tq]
            unsigned pa1 = f2tf(odd ? c1f : c0f); // P[r0+8][8nb+tq]
            unsigned pa2 = f2tf(odd ? b1f : b0f); // P[r0][8nb+tq+4]
            unsigned pa3 = f2tf(odd ? d1f : d0f); // P[r0+8][8nb+tq+4]

            // ---- O += P(:,block nb) * V(block nb, :) ----
            #pragma unroll
            for (int nd = 0; nd < 8; nd++) {
                unsigned vb0 = Vu[(8 * nb + tq)     * PV + 8 * nd + g];
                unsigned vb1 = Vu[(8 * nb + tq + 4) * PV + 8 * nd + g];
                mma_tf32(oacc[nd], pa0, pa1, pa2, pa3, vb0, vb1);
            }
        }
    }

    // ---- epilogue: quad-reduce row sums, write unnormalized partials ----
    lsum0 += __shfl_xor_sync(0xffffffffu, lsum0, 1);
    lsum0 += __shfl_xor_sync(0xffffffffu, lsum0, 2);
    lsum1 += __shfl_xor_sync(0xffffffffu, lsum1, 1);
    lsum1 += __shfl_xor_sync(0xffffffffu, lsum1, 2);

    const size_t rowbase = (size_t)z * BATCH * SEQ + (size_t)b * SEQ + q0;
    if (tq == 0) {
        g_lsum[rowbase + r0]     = lsum0;
        g_lsum[rowbase + r0 + 8] = lsum1;
    }
    float* o0 = g_part + (rowbase + r0)     * HD;
    float* o1 = g_part + (rowbase + r0 + 8) * HD;
    #pragma unroll
    for (int n = 0; n < 8; n++) {
        int cc = 8 * n + 2 * tq;
        *reinterpret_cast<float2*>(&o0[cc]) = make_float2(oacc[n][0], oacc[n][1]);
        *reinterpret_cast<float2*>(&o1[cc]) = make_float2(oacc[n][2], oacc[n][3]);
    }
}

// ---------------------------------------------------------------------------
// Combine: out = (sum_z O_z) / (sum_z l_z)
// ---------------------------------------------------------------------------
__global__ __launch_bounds__(256) void combine_kernel(float* __restrict__ out)
{
    const int idx = blockIdx.x * blockDim.x + threadIdx.x;  // 262144 float4
    const int row = idx >> 4;
    const int c4  = idx & 15;
    const size_t stride = (size_t)BATCH * SEQ;

    float l = 0.0f;
    float4 o = make_float4(0.f, 0.f, 0.f, 0.f);
    #pragma unroll
    for (int zz = 0; zz < NSPLIT; zz++) {
        l += g_lsum[zz * stride + row];
        float4 p = *reinterpret_cast<const float4*>(
            &g_part[(zz * stride + row) * HD + c4 * 4]);
        o.x += p.x; o.y += p.y; o.z += p.z; o.w += p.w;
    }
    float inv = 1.0f / l;
    o.x *= inv; o.y *= inv; o.z *= inv; o.w *= inv;
    *reinterpret_cast<float4*>(&out[(size_t)row * HD + c4 * 4]) = o;
}

// ---------------------------------------------------------------------------
extern "C" void kernel_launch(void* const* d_in, const int* in_sizes, int n_in,
                              void* d_out, int out_size)
{
    const float* x  = (const float*)d_in[0];
    const float* WQ = (const float*)d_in[1];
    const float* WK = (const float*)d_in[2];
    const float* WV = (const float*)d_in[3];
    float* out = (float*)d_out;

    cudaFuncSetAttribute(attn_mma_kernel,
                         cudaFuncAttributeMaxDynamicSharedMemorySize,
                         ATTN_SMEM_BYTES);

    proj_mma_kernel<<<dim3(SEQ * BATCH / 64, 3), 128, PROJ_SMEM_BYTES>>>(x, WQ, WK, WV);
    attn_mma_kernel<<<dim3(SEQ / 64, BATCH, NSPLIT), 128, ATTN_SMEM_BYTES>>>();
    combine_kernel<<<(BATCH * SEQ * HD / 4) / 256, 256>>>(out);
}

// round 7
// speedup vs baseline: 1.2795x; 1.2795x over previous
#include <cuda_runtime.h>
#include <math.h>

#define BATCH 4
#define SEQ   4096
#define EMB   512
#define HD    64
#define NSPLIT 7

__device__ float g_q[BATCH * SEQ * HD];
__device__ float g_k[BATCH * SEQ * HD];
__device__ float g_v[BATCH * SEQ * HD];
__device__ float g_part[NSPLIT * BATCH * SEQ * HD];   // unnormalized O partials
__device__ float g_lsum[NSPLIT * BATCH * SEQ];        // exp-sum partials

// ---------------------------------------------------------------------------
__device__ __forceinline__ unsigned f2tf(float x) {
    unsigned r;
    asm("cvt.rna.tf32.f32 %0, %1;" : "=r"(r) : "f"(x));
    return r;
}
__device__ __forceinline__ float ex2(float x) {
    float r;
    asm("ex2.approx.ftz.f32 %0, %1;" : "=f"(r) : "f"(x));
    return r;
}

__device__ __forceinline__ void mma_tf32(float c[4],
                                         unsigned a0, unsigned a1,
                                         unsigned a2, unsigned a3,
                                         unsigned b0, unsigned b1) {
    asm volatile(
        "mma.sync.aligned.m16n8k8.row.col.f32.tf32.tf32.f32 "
        "{%0,%1,%2,%3}, {%4,%5,%6,%7}, {%8,%9}, {%0,%1,%2,%3};"
        : "+f"(c[0]), "+f"(c[1]), "+f"(c[2]), "+f"(c[3])
        : "r"(a0), "r"(a1), "r"(a2), "r"(a3), "r"(b0), "r"(b1));
}

#define CP_COMMIT() asm volatile("cp.async.commit_group;" ::: "memory")
#define CP_WAIT1()  asm volatile("cp.async.wait_group 1;" ::: "memory")

// ---------------------------------------------------------------------------
// tf32 projection: C[16384,64] = X[16384,512] * W[64,512]^T.
// Convert-at-STS (tf32 smem, no per-use cvt) + register-prefetch of the
// next 64-wide K chunk overlapped with the mma phase.
// ---------------------------------------------------------------------------
#define PP 68
#define PNCHUNK (EMB / 64)   // 8

__global__ __launch_bounds__(128) void proj_mma_kernel(
    const float* __restrict__ x,
    const float* __restrict__ WQ,
    const float* __restrict__ WK,
    const float* __restrict__ WV)
{
    __shared__ float Xs[64 * PP];
    __shared__ float Ws[64 * PP];

    const float* W;
    float* out;
    if (blockIdx.y == 0)      { W = WQ; out = g_q; }
    else if (blockIdx.y == 1) { W = WK; out = g_k; }
    else                      { W = WV; out = g_v; }

    const int tid  = threadIdx.x;
    const int lane = tid & 31;
    const int warp = tid >> 5;
    const int g    = lane >> 2;
    const int tq   = lane & 3;
    const int bm   = blockIdx.x * 64;
    const int r0   = 16 * warp + g;

    // per-thread slots: 8 float4 of X, 8 of W (64 rows x 16 float4-cols)
    int srow[8], sc4[8];
    #pragma unroll
    for (int i = 0; i < 8; i++) {
        int f = tid + 128 * i;
        srow[i] = f >> 4;
        sc4[i]  = f & 15;
    }

    float4 xr[8], wr[8];
    #pragma unroll
    for (int i = 0; i < 8; i++) {
        xr[i] = *reinterpret_cast<const float4*>(
            &x[(size_t)(bm + srow[i]) * EMB + sc4[i] * 4]);
        wr[i] = *reinterpret_cast<const float4*>(
            &W[(size_t)srow[i] * EMB + sc4[i] * 4]);
    }

    const unsigned* Xu = reinterpret_cast<const unsigned*>(Xs);
    const unsigned* Wu = reinterpret_cast<const unsigned*>(Ws);

    float acc[8][4];
    #pragma unroll
    for (int n = 0; n < 8; n++)
        #pragma unroll
        for (int j = 0; j < 4; j++) acc[n][j] = 0.0f;

    for (int c = 0; c < PNCHUNK; c++) {
        __syncthreads();   // previous chunk's fragment reads done
        #pragma unroll
        for (int i = 0; i < 8; i++) {
            uint4 xt = { f2tf(xr[i].x), f2tf(xr[i].y), f2tf(xr[i].z), f2tf(xr[i].w) };
            *reinterpret_cast<uint4*>(&Xs[srow[i] * PP + sc4[i] * 4]) = xt;
            uint4 wt = { f2tf(wr[i].x), f2tf(wr[i].y), f2tf(wr[i].z), f2tf(wr[i].w) };
            *reinterpret_cast<uint4*>(&Ws[srow[i] * PP + sc4[i] * 4]) = wt;
        }
        // prefetch next chunk while mma runs
        if (c + 1 < PNCHUNK) {
            int k0 = (c + 1) * 64;
            #pragma unroll
            for (int i = 0; i < 8; i++) {
                xr[i] = *reinterpret_cast<const float4*>(
                    &x[(size_t)(bm + srow[i]) * EMB + k0 + sc4[i] * 4]);
                wr[i] = *reinterpret_cast<const float4*>(
                    &W[(size_t)srow[i] * EMB + k0 + sc4[i] * 4]);
            }
        }
        __syncthreads();   // smem tiles ready

        unsigned xa[8][4];
        #pragma unroll
        for (int ks = 0; ks < 8; ks++) {
            int kk = ks * 8;
            xa[ks][0] = Xu[(r0)     * PP + kk + tq];
            xa[ks][1] = Xu[(r0 + 8) * PP + kk + tq];
            xa[ks][2] = Xu[(r0)     * PP + kk + tq + 4];
            xa[ks][3] = Xu[(r0 + 8) * PP + kk + tq + 4];
        }
        #pragma unroll
        for (int n = 0; n < 8; n++) {
            #pragma unroll
            for (int ks = 0; ks < 8; ks++) {
                unsigned b0 = Wu[(8 * n + g) * PP + 8 * ks + tq];
                unsigned b1 = Wu[(8 * n + g) * PP + 8 * ks + tq + 4];
                mma_tf32(acc[n], xa[ks][0], xa[ks][1], xa[ks][2], xa[ks][3], b0, b1);
            }
        }
    }

    // store PRE-ROUNDED to tf32 (attention consumes without cvt)
    float* o0 = out + (size_t)(bm + r0)     * HD;
    float* o1 = out + (size_t)(bm + r0 + 8) * HD;
    #pragma unroll
    for (int n = 0; n < 8; n++) {
        int cc = 8 * n + 2 * tq;
        float2 w0 = { __uint_as_float(f2tf(acc[n][0])), __uint_as_float(f2tf(acc[n][1])) };
        float2 w1 = { __uint_as_float(f2tf(acc[n][2])), __uint_as_float(f2tf(acc[n][3])) };
        *reinterpret_cast<float2*>(&o0[cc]) = w0;
        *reinterpret_cast<float2*>(&o1[cc]) = w1;
    }
}

// ---------------------------------------------------------------------------
// Attention: tf32 mma, m32 warp tile (two m16 A-tiles share every B-frag),
// CTA = 128 Q rows / 4 warps, split-KV, cp.async double-buffered K/V,
// shuffle-based S->P conversion, no-max softmax.
// ---------------------------------------------------------------------------
#define PK   68
#define PV   72
#define KBUF (64 * PK)
#define VBUF (64 * PV)
#define ATTN_SMEM_BYTES ((2 * KBUF + 2 * VBUF) * 4)

__device__ __forceinline__ void attn_load_async(float* Kd, float* Vd,
                                                const float* kg, const float* vg,
                                                int tid) {
    unsigned ka = (unsigned)__cvta_generic_to_shared(Kd);
    unsigned va = (unsigned)__cvta_generic_to_shared(Vd);
    #pragma unroll
    for (int i = 0; i < 8; i++) {
        int f = tid + 128 * i;           // 1024 float4 = 64 rows x 16
        int row = f >> 4, c4 = f & 15;
        asm volatile("cp.async.cg.shared.global [%0], [%1], 16;" ::
            "r"(ka + (unsigned)((row * PK + c4 * 4) * 4)),
            "l"(kg + row * HD + c4 * 4) : "memory");
        asm volatile("cp.async.cg.shared.global [%0], [%1], 16;" ::
            "r"(va + (unsigned)((row * PV + c4 * 4) * 4)),
            "l"(vg + row * HD + c4 * 4) : "memory");
    }
}

__global__ __launch_bounds__(128) void attn_mma_kernel()
{
    extern __shared__ float sm[];
    float* Kb[2] = { sm, sm + KBUF };
    float* Vb[2] = { sm + 2 * KBUF, sm + 2 * KBUF + VBUF };

    const int tid  = threadIdx.x;
    const int lane = tid & 31;
    const int warp = tid >> 5;
    const int g    = lane >> 2;
    const int tq   = lane & 3;
    const int b    = blockIdx.y;
    const int q0   = blockIdx.x * 128;
    const int z    = blockIdx.z;
    const int t_begin = (64 * z) / NSPLIT;
    const int t_end   = (64 * (z + 1)) / NSPLIT;
    const int nt      = t_end - t_begin;

    const float* qg  = g_q + ((size_t)b * SEQ + q0) * HD;
    const float* kgb = g_k + ((size_t)b * SEQ + (size_t)t_begin * 64) * HD;
    const float* vgb = g_v + ((size_t)b * SEQ + (size_t)t_begin * 64) * HD;

    // warp handles rows [32*warp, 32*warp+32): halves h=0,1 -> m16 row sets
    const int rw = 32 * warp;
    unsigned qa[2][8][4];
    #pragma unroll
    for (int h = 0; h < 2; h++) {
        int ra = rw + 16 * h + g;
        #pragma unroll
        for (int ks = 0; ks < 8; ks++) {
            qa[h][ks][0] = __float_as_uint(qg[(ra)     * HD + 8 * ks + tq]);
            qa[h][ks][1] = __float_as_uint(qg[(ra + 8) * HD + 8 * ks + tq]);
            qa[h][ks][2] = __float_as_uint(qg[(ra)     * HD + 8 * ks + tq + 4]);
            qa[h][ks][3] = __float_as_uint(qg[(ra + 8) * HD + 8 * ks + tq + 4]);
        }
    }

    float oacc[2][8][4];
    #pragma unroll
    for (int h = 0; h < 2; h++)
        #pragma unroll
        for (int n = 0; n < 8; n++)
            #pragma unroll
            for (int j = 0; j < 4; j++) oacc[h][n][j] = 0.0f;
    float ls[2][2] = {{0.f, 0.f}, {0.f, 0.f}};

    attn_load_async(Kb[0], Vb[0], kgb, vgb, tid);
    CP_COMMIT();

    const float C = 0.18033688f;   // 0.125 * log2(e)

    for (int tt = 0; tt < nt; tt++) {
        __syncthreads();
        if (tt + 1 < nt)
            attn_load_async(Kb[(tt + 1) & 1], Vb[(tt + 1) & 1],
                            kgb + (size_t)(tt + 1) * 64 * HD,
                            vgb + (size_t)(tt + 1) * 64 * HD, tid);
        CP_COMMIT();
        CP_WAIT1();
        __syncthreads();

        const unsigned* Ku = reinterpret_cast<const unsigned*>(Kb[tt & 1]);
        const unsigned* Vu = reinterpret_cast<const unsigned*>(Vb[tt & 1]);

        #pragma unroll
        for (int nb = 0; nb < 8; nb++) {
            // ---- S block: both halves share the K B-fragments ----
            float cf[2][4] = {{0.f,0.f,0.f,0.f},{0.f,0.f,0.f,0.f}};
            #pragma unroll
            for (int kc = 0; kc < 8; kc++) {
                unsigned b0 = Ku[(8 * nb + g) * PK + 8 * kc + tq];
                unsigned b1 = Ku[(8 * nb + g) * PK + 8 * kc + tq + 4];
                mma_tf32(cf[0], qa[0][kc][0], qa[0][kc][1], qa[0][kc][2], qa[0][kc][3], b0, b1);
                mma_tf32(cf[1], qa[1][kc][0], qa[1][kc][1], qa[1][kc][2], qa[1][kc][3], b0, b1);
            }

            // ---- exp + C-frag -> A-frag conversion (per half) ----
            unsigned pa[2][4];
            #pragma unroll
            for (int h = 0; h < 2; h++) {
                float e0 = ex2(cf[h][0] * C);
                float e1 = ex2(cf[h][1] * C);
                float e2 = ex2(cf[h][2] * C);
                float e3 = ex2(cf[h][3] * C);
                ls[h][0] += e0 + e1;
                ls[h][1] += e2 + e3;
                int hh = tq >> 1;
                float a0  = __shfl_sync(0xffffffffu, e0, hh, 4);
                float a1  = __shfl_sync(0xffffffffu, e1, hh, 4);
                float b0f = __shfl_sync(0xffffffffu, e0, hh + 2, 4);
                float b1f = __shfl_sync(0xffffffffu, e1, hh + 2, 4);
                float c0f = __shfl_sync(0xffffffffu, e2, hh, 4);
                float c1f = __shfl_sync(0xffffffffu, e3, hh, 4);
                float d0f = __shfl_sync(0xffffffffu, e2, hh + 2, 4);
                float d1f = __shfl_sync(0xffffffffu, e3, hh + 2, 4);
                bool odd = (tq & 1);
                pa[h][0] = f2tf(odd ? a1  : a0);    // P[rA][8nb+tq]
                pa[h][1] = f2tf(odd ? c1f : c0f);   // P[rB][8nb+tq]
                pa[h][2] = f2tf(odd ? b1f : b0f);   // P[rA][8nb+tq+4]
                pa[h][3] = f2tf(odd ? d1f : d0f);   // P[rB][8nb+tq+4]
            }

            // ---- O += P(:,nb) * V(nb,:) ; both halves share V B-frags ----
            #pragma unroll
            for (int nd = 0; nd < 8; nd++) {
                unsigned vb0 = Vu[(8 * nb + tq)     * PV + 8 * nd + g];
                unsigned vb1 = Vu[(8 * nb + tq + 4) * PV + 8 * nd + g];
                mma_tf32(oacc[0][nd], pa[0][0], pa[0][1], pa[0][2], pa[0][3], vb0, vb1);
                mma_tf32(oacc[1][nd], pa[1][0], pa[1][1], pa[1][2], pa[1][3], vb0, vb1);
            }
        }
    }

    // ---- epilogue: quad-reduce sums, write unnormalized partials ----
    const size_t rowbase = (size_t)z * BATCH * SEQ + (size_t)b * SEQ + q0;
    #pragma unroll
    for (int h = 0; h < 2; h++) {
        float l0 = ls[h][0], l1 = ls[h][1];
        l0 += __shfl_xor_sync(0xffffffffu, l0, 1);
        l0 += __shfl_xor_sync(0xffffffffu, l0, 2);
        l1 += __shfl_xor_sync(0xffffffffu, l1, 1);
        l1 += __shfl_xor_sync(0xffffffffu, l1, 2);
        int ra = rw + 16 * h + g;
        if (tq == 0) {
            g_lsum[rowbase + ra]     = l0;
            g_lsum[rowbase + ra + 8] = l1;
        }
        float* o0 = g_part + (rowbase + ra)     * HD;
        float* o1 = g_part + (rowbase + ra + 8) * HD;
        #pragma unroll
        for (int n = 0; n < 8; n++) {
            int cc = 8 * n + 2 * tq;
            *reinterpret_cast<float2*>(&o0[cc]) = make_float2(oacc[h][n][0], oacc[h][n][1]);
            *reinterpret_cast<float2*>(&o1[cc]) = make_float2(oacc[h][n][2], oacc[h][n][3]);
        }
    }
}

// ---------------------------------------------------------------------------
// Combine: out = (sum_z O_z) / (sum_z l_z)
// ---------------------------------------------------------------------------
__global__ __launch_bounds__(256) void combine_kernel(float* __restrict__ out)
{
    const int idx = blockIdx.x * blockDim.x + threadIdx.x;  // 262144 float4
    const int row = idx >> 4;
    const int c4  = idx & 15;
    const size_t stride = (size_t)BATCH * SEQ;

    float l = 0.0f;
    float4 o = make_float4(0.f, 0.f, 0.f, 0.f);
    #pragma unroll
    for (int zz = 0; zz < NSPLIT; zz++) {
        l += g_lsum[zz * stride + row];
        float4 p = *reinterpret_cast<const float4*>(
            &g_part[(zz * stride + row) * HD + c4 * 4]);
        o.x += p.x; o.y += p.y; o.z += p.z; o.w += p.w;
    }
    float inv = 1.0f / l;
    o.x *= inv; o.y *= inv; o.z *= inv; o.w *= inv;
    *reinterpret_cast<float4*>(&out[(size_t)row * HD + c4 * 4]) = o;
}

// ---------------------------------------------------------------------------
extern "C" void kernel_launch(void* const* d_in, const int* in_sizes, int n_in,
                              void* d_out, int out_size)
{
    const float* x  = (const float*)d_in[0];
    const float* WQ = (const float*)d_in[1];
    const float* WK = (const float*)d_in[2];
    const float* WV = (const float*)d_in[3];
    float* out = (float*)d_out;

    cudaFuncSetAttribute(attn_mma_kernel,
                         cudaFuncAttributeMaxDynamicSharedMemorySize,
                         ATTN_SMEM_BYTES);

    proj_mma_kernel<<<dim3(SEQ * BATCH / 64, 3), 128>>>(x, WQ, WK, WV);
    attn_mma_kernel<<<dim3(SEQ / 128, BATCH, NSPLIT), 128, ATTN_SMEM_BYTES>>>();
    combine_kernel<<<(BATCH * SEQ * HD / 4) / 256, 256>>>(out);
}